// round 4
// baseline (speedup 1.0000x reference)
#include <cuda_runtime.h>
#include <cuda_bf16.h>
#include <math.h>
#include <stdint.h>

#define BSZ   16
#define NJ    24
#define NH    8
#define DHD   32
#define DIN   256
#define NTOK  1152
#define MROWS 18432        /* BSZ*NTOK */
#define EPSV  1e-6f

/* ---------------- scratch ---------------- */
__device__ __nv_bfloat16 g_xhi[(size_t)MROWS * DIN];
__device__ __nv_bfloat16 g_xlo[(size_t)MROWS * DIN];
__device__ __nv_bfloat16 g_wthi[3 * DIN * DIN];   /* [sel*256+n][k] transposed */
__device__ __nv_bfloat16 g_wtlo[3 * DIN * DIN];
__device__ float g_qkv[3ull * BSZ * NH * NTOK * DHD];   /* [sel*128 + b*8+h][tok][32] */

/* ---------------- conversion: fp32 -> bf16 hi/lo (+ W transpose) -------- */
__global__ __launch_bounds__(256) void cvt_kernel(
    const float* __restrict__ x, const float* __restrict__ Wq,
    const float* __restrict__ Wk, const float* __restrict__ Wv)
{
    int b = blockIdx.x;
    if (b < 4608) {                         /* x: 1,179,648 float4s */
        int idx = b * 256 + threadIdx.x;
        float4 v = ((const float4*)x)[idx];
        float vv[4] = { v.x, v.y, v.z, v.w };
        ushort4 h4, l4;
        unsigned short* hp = &h4.x;
        unsigned short* lp = &l4.x;
#pragma unroll
        for (int c = 0; c < 4; c++) {
            __nv_bfloat16 hb = __float2bfloat16(vv[c]);
            __nv_bfloat16 lb = __float2bfloat16(vv[c] - __bfloat162float(hb));
            hp[c] = __bfloat16_as_ushort(hb);
            lp[c] = __bfloat16_as_ushort(lb);
        }
        ((ushort4*)g_xhi)[idx] = h4;
        ((ushort4*)g_xlo)[idx] = l4;
    } else {                                /* W transpose: 196,608 elems */
        int e = (b - 4608) * 256 + threadIdx.x;
        int ws = e >> 16;
        int r  = e & 65535;
        int n  = r >> 8;
        int k  = r & 255;
        const float* W = (ws == 0) ? Wq : (ws == 1 ? Wk : Wv);
        float v = W[k * 256 + n];
        __nv_bfloat16 hb = __float2bfloat16(v);
        __nv_bfloat16 lb = __float2bfloat16(v - __bfloat162float(hb));
        g_wthi[ws * 65536 + n * 256 + k] = hb;
        g_wtlo[ws * 65536 + n * 256 + k] = lb;
    }
}

/* ---------------- mma.sync bf16x3 GEMM, ldmatrix + cp.async double-buffer ----
 * C[18432, 768] = x @ Wcat^T. CTA: 128x128, 8 warps (4x2), warp tile 32x64.
 * K in 64-chunks; smem row stride 72 bf16 (144 B = 9 chunks -> LDSM conflict-free).
 */
#define KST 72
#define TILE_BYTES (128 * KST * 2)          /* 18432 */
#define STAGE_BYTES (4 * TILE_BYTES)        /* Ah Al Bh Bl = 73728 */
#define SMEM_GEMM (2 * STAGE_BYTES)         /* 147456 */

__device__ __forceinline__ void mma16816(float* c, const uint32_t* a, const uint32_t* b) {
    asm volatile("mma.sync.aligned.m16n8k16.row.col.f32.bf16.bf16.f32 "
        "{%0,%1,%2,%3}, {%4,%5,%6,%7}, {%8,%9}, {%0,%1,%2,%3};"
        : "+f"(c[0]), "+f"(c[1]), "+f"(c[2]), "+f"(c[3])
        : "r"(a[0]), "r"(a[1]), "r"(a[2]), "r"(a[3]), "r"(b[0]), "r"(b[1]));
}
__device__ __forceinline__ void ldsm_x4(uint32_t* r, uint32_t addr) {
    asm volatile("ldmatrix.sync.aligned.m8n8.x4.shared.b16 {%0,%1,%2,%3}, [%4];"
        : "=r"(r[0]), "=r"(r[1]), "=r"(r[2]), "=r"(r[3]) : "r"(addr));
}
__device__ __forceinline__ void cp16(uint32_t dst, const void* src) {
    asm volatile("cp.async.cg.shared.global [%0], [%1], 16;" :: "r"(dst), "l"(src));
}
#define CP_COMMIT() asm volatile("cp.async.commit_group;" ::: "memory")
#define CP_WAIT(n)  asm volatile("cp.async.wait_group %0;" :: "n"(n) : "memory")

__device__ __forceinline__ uint32_t smem_u32(const void* p) {
    uint32_t a;
    asm("{ .reg .u64 t; cvta.to.shared.u64 t, %1; cvt.u32.u64 %0, t; }" : "=r"(a) : "l"(p));
    return a;
}

__global__ __launch_bounds__(256) void gemm_kernel(
    const float* __restrict__ bq, const float* __restrict__ bk, const float* __restrict__ bv)
{
    extern __shared__ char smc[];
    const uint32_t sb = smem_u32(smc);

    const int tid  = threadIdx.x;
    const int wid  = tid >> 5, lane = tid & 31;
    const int gid  = lane >> 2, tig = lane & 3;
    const int m0   = blockIdx.x * 128;
    const int n0   = blockIdx.y * 128;
    const int rbase = (wid & 3) * 32;
    const int nbase = (wid >> 2) * 64;

    /* per-lane ldmatrix quadrant offsets */
    const int mq = lane >> 3;
    const int laneRowA = (mq & 1) * 8 + (lane & 7);
    const int laneColA = (mq >> 1) * 8;
    const int laneRowB = (mq >> 1) * 8 + (lane & 7);
    const int laneColB = (mq & 1) * 8;

    /* staging addressing (per-thread constants) */
    const int sr = tid >> 3;          /* 0..31  (+32 per it) */
    const int sg = tid & 7;
    const uint32_t dstOff = (uint32_t)(sr * 144 + sg * 16);

    float c[2][8][4];
#pragma unroll
    for (int mt = 0; mt < 2; mt++)
#pragma unroll
        for (int nt = 0; nt < 8; nt++)
#pragma unroll
            for (int q = 0; q < 4; q++) c[mt][nt][q] = 0.f;

    /* ---- stage chunk ch into buffer s ---- */
    auto stage = [&](int ch, int s) {
        const int k0 = ch * 64;
        const uint32_t base = sb + (uint32_t)s * STAGE_BYTES;
#pragma unroll
        for (int it = 0; it < 4; it++) {
            int r = sr + it * 32;
            size_t srcA = (size_t)(m0 + r) * 256 + k0 + sg * 8;
            size_t srcB = (size_t)(n0 + r) * 256 + k0 + sg * 8;
            uint32_t d = dstOff + (uint32_t)it * 32 * 144;
            cp16(base + 0 * TILE_BYTES + d, g_xhi  + srcA);
            cp16(base + 1 * TILE_BYTES + d, g_xlo  + srcA);
            cp16(base + 2 * TILE_BYTES + d, g_wthi + srcB);
            cp16(base + 3 * TILE_BYTES + d, g_wtlo + srcB);
        }
    };

    stage(0, 0);
    CP_COMMIT();

    for (int ch = 0; ch < 4; ch++) {
        const int s = ch & 1;
        if (ch < 3) {
            stage(ch + 1, s ^ 1);
            CP_COMMIT();
            CP_WAIT(1);
        } else {
            CP_WAIT(0);
        }
        __syncthreads();

        const uint32_t base = sb + (uint32_t)s * STAGE_BYTES;
        const uint32_t aHi = base + 0 * TILE_BYTES;
        const uint32_t aLo = base + 1 * TILE_BYTES;
        const uint32_t bHi = base + 2 * TILE_BYTES;
        const uint32_t bLo = base + 3 * TILE_BYTES;

#pragma unroll
        for (int ks = 0; ks < 4; ks++) {
            uint32_t ah[2][4], al[2][4];
#pragma unroll
            for (int mt = 0; mt < 2; mt++) {
                uint32_t ao = (uint32_t)((rbase + mt * 16 + laneRowA) * KST
                                         + ks * 16 + laneColA) * 2;
                ldsm_x4(ah[mt], aHi + ao);
                ldsm_x4(al[mt], aLo + ao);
            }
#pragma unroll
            for (int ntp = 0; ntp < 4; ntp++) {
                uint32_t bo = (uint32_t)((nbase + ntp * 16 + laneRowB) * KST
                                         + ks * 16 + laneColB) * 2;
                uint32_t bh[4], bl[4];
                ldsm_x4(bh, bHi + bo);
                ldsm_x4(bl, bLo + bo);
#pragma unroll
                for (int mt = 0; mt < 2; mt++) {
                    mma16816(c[mt][2 * ntp],     ah[mt], bh);       /* hi*hi */
                    mma16816(c[mt][2 * ntp],     ah[mt], bl);       /* hi*lo */
                    mma16816(c[mt][2 * ntp],     al[mt], bh);       /* lo*hi */
                    mma16816(c[mt][2 * ntp + 1], ah[mt], bh + 2);
                    mma16816(c[mt][2 * ntp + 1], ah[mt], bl + 2);
                    mma16816(c[mt][2 * ntp + 1], al[mt], bh + 2);
                }
            }
        }
        __syncthreads();
    }

    /* epilogue: bias (+relu on V), write head-major (identical to R3)  */
    const int sel = n0 >> 8;
    const float* bias = (sel == 0) ? bq : (sel == 1 ? bk : bv);
    const int bb = m0 / NTOK;
    const int tokbase = m0 % NTOK;
    float* outsel = g_qkv + ((size_t)(sel * 128 + bb * 8)) * NTOK * DHD;

#pragma unroll
    for (int mt = 0; mt < 2; mt++) {
        int r0 = tokbase + rbase + mt * 16 + gid;
#pragma unroll
        for (int nt = 0; nt < 8; nt++) {
            int cn = (n0 & 255) + nbase + nt * 8 + tig * 2;
            int h = cn >> 5, d = cn & 31;
            float bi0 = bias[cn], bi1 = bias[cn + 1];
            float v0 = c[mt][nt][0] + bi0, v1 = c[mt][nt][1] + bi1;
            float v2 = c[mt][nt][2] + bi0, v3 = c[mt][nt][3] + bi1;
            if (sel == 2) {
                v0 = fmaxf(v0, 0.f); v1 = fmaxf(v1, 0.f);
                v2 = fmaxf(v2, 0.f); v3 = fmaxf(v3, 0.f);
            }
            float* p0 = outsel + ((size_t)h * NTOK + r0) * DHD + d;
            *(float2*)p0 = make_float2(v0, v1);
            *(float2*)(p0 + 8 * DHD) = make_float2(v2, v3);
        }
    }
}

/* ---------------- attention: warp per (b, h, frame) — unchanged from R3 ------ */
#define SWST 28

__global__ __launch_bounds__(256) void attn_kernel(float* __restrict__ out)
{
    __shared__ float sw[8 * 32 * SWST];
    const int bh   = blockIdx.x;
    const int wid  = threadIdx.x >> 5;
    const int lane = threadIdx.x & 31;
    const int frame = blockIdx.y * 8 + wid;

    const float* qb = g_qkv + ((size_t)bh * NTOK + (size_t)frame * NJ) * DHD;
    const float* kb = g_qkv + ((size_t)(128 + bh) * NTOK + (size_t)frame * NJ) * DHD;
    const float* vb = g_qkv + ((size_t)(256 + bh) * NTOK + (size_t)frame * NJ) * DHD;

    float* sc = sw + wid * 32 * SWST;

#pragma unroll
    for (int r = 0; r < NJ; r++)
        sc[lane * SWST + r] = qb[r * DHD + lane];
    __syncwarp();

    const int j = (lane < NJ) ? lane : 0;
    float kreg[DHD];
    {
        const float4* kp = (const float4*)(kb + j * DHD);
#pragma unroll
        for (int cc = 0; cc < 8; cc++) {
            float4 kk = kp[cc];
            kreg[4*cc] = kk.x; kreg[4*cc+1] = kk.y; kreg[4*cc+2] = kk.z; kreg[4*cc+3] = kk.w;
        }
    }
    float s[NJ];
#pragma unroll
    for (int i = 0; i < NJ; i++) s[i] = 0.f;
#pragma unroll
    for (int d = 0; d < DHD; d++) {
        float kd = kreg[d];
#pragma unroll
        for (int i4 = 0; i4 < 6; i4++) {
            float4 q4 = *(const float4*)&sc[d * SWST + i4 * 4];
            s[i4*4+0] = fmaf(q4.x, kd, s[i4*4+0]);
            s[i4*4+1] = fmaf(q4.y, kd, s[i4*4+1]);
            s[i4*4+2] = fmaf(q4.z, kd, s[i4*4+2]);
            s[i4*4+3] = fmaf(q4.w, kd, s[i4*4+3]);
        }
    }
    const float scale = 0.17677669529663688f;
#pragma unroll
    for (int i = 0; i < NJ; i++)
        s[i] = (lane < NJ) ? s[i] * scale : -3.402823466e38f;

    __syncwarp();
    float w_[NJ];
#pragma unroll
    for (int i = 0; i < NJ; i++) {
        float m = s[i];
#pragma unroll
        for (int off = 16; off > 0; off >>= 1)
            m = fmaxf(m, __shfl_xor_sync(0xffffffffu, m, off));
        float e = __expf(s[i] - m);
        float sum = e;
#pragma unroll
        for (int off = 16; off > 0; off >>= 1)
            sum += __shfl_xor_sync(0xffffffffu, sum, off);
        w_[i] = e / (sum + EPSV);
    }

    if (lane < NJ) {
#pragma unroll
        for (int i = 0; i < NJ; i++)
            sc[lane * SWST + i] = w_[i];
    }
    __syncwarp();

    float vreg[NJ];
#pragma unroll
    for (int jj = 0; jj < NJ; jj++)
        vreg[jj] = vb[jj * DHD + lane];
    float o[NJ];
#pragma unroll
    for (int i = 0; i < NJ; i++) o[i] = 0.f;
#pragma unroll
    for (int jj = 0; jj < NJ; jj++) {
        float vj = vreg[jj];
#pragma unroll
        for (int i4 = 0; i4 < 6; i4++) {
            float4 a4 = *(const float4*)&sc[jj * SWST + i4 * 4];
            o[i4*4+0] = fmaf(a4.x, vj, o[i4*4+0]);
            o[i4*4+1] = fmaf(a4.y, vj, o[i4*4+1]);
            o[i4*4+2] = fmaf(a4.z, vj, o[i4*4+2]);
            o[i4*4+3] = fmaf(a4.w, vj, o[i4*4+3]);
        }
    }

    const int b = bh >> 3, h = bh & 7;
    float* od = out + ((size_t)b * NTOK + (size_t)frame * NJ) * DIN + h * DHD + lane;
#pragma unroll
    for (int i = 0; i < NJ; i++)
        od[(size_t)i * DIN] = o[i];
}

/* ---------------- launch ---------------- */
extern "C" void kernel_launch(void* const* d_in, const int* in_sizes, int n_in,
                              void* d_out, int out_size)
{
    const float* x  = (const float*)d_in[0];
    const float* Wq = (const float*)d_in[1];
    const float* bq = (const float*)d_in[2];
    const float* Wk = (const float*)d_in[3];
    const float* bk = (const float*)d_in[4];
    const float* Wv = (const float*)d_in[5];
    const float* bv = (const float*)d_in[6];
    float* out = (float*)d_out;

    cvt_kernel<<<4608 + 768, 256>>>(x, Wq, Wk, Wv);

    cudaFuncSetAttribute(gemm_kernel, cudaFuncAttributeMaxDynamicSharedMemorySize, SMEM_GEMM);
    gemm_kernel<<<dim3(144, 6), 256, SMEM_GEMM>>>(bq, bk, bv);

    attn_kernel<<<dim3(128, 6), 256>>>(out);
}

// round 5
// speedup vs baseline: 1.3779x; 1.3779x over previous
#include <cuda_runtime.h>
#include <cuda_fp16.h>
#include <math.h>
#include <stdint.h>

#define BSZ   16
#define NJ    24
#define NH    8
#define DHD   32
#define DIN   256
#define NTOK  1152
#define MROWS 18432        /* BSZ*NTOK */
#define EPSV  1e-6f

/* ---------------- scratch ---------------- */
__device__ __half g_xh[(size_t)MROWS * DIN];
__device__ __half g_wt[3 * DIN * DIN];            /* [sel*256+n][k] transposed */
__device__ float g_qkv[3ull * BSZ * NH * NTOK * DHD];   /* [sel*128 + b*8+h][tok][32] */

/* ---------------- conversion: fp32 -> fp16 (+ W transpose) -------- */
__global__ __launch_bounds__(256) void cvt_kernel(
    const float* __restrict__ x, const float* __restrict__ Wq,
    const float* __restrict__ Wk, const float* __restrict__ Wv)
{
    int b = blockIdx.x;
    if (b < 4608) {                         /* x: 1,179,648 float4s */
        int idx = b * 256 + threadIdx.x;
        float4 v = ((const float4*)x)[idx];
        __half2 h0 = __floats2half2_rn(v.x, v.y);
        __half2 h1 = __floats2half2_rn(v.z, v.w);
        uint2 pk;
        pk.x = *(uint32_t*)&h0;
        pk.y = *(uint32_t*)&h1;
        ((uint2*)g_xh)[idx] = pk;
    } else {                                /* W transpose: 196,608 elems */
        int e = (b - 4608) * 256 + threadIdx.x;
        int ws = e >> 16;
        int r  = e & 65535;
        int n  = r >> 8;
        int k  = r & 255;
        const float* W = (ws == 0) ? Wq : (ws == 1 ? Wk : Wv);
        g_wt[ws * 65536 + n * 256 + k] = __float2half_rn(W[k * 256 + n]);
    }
}

/* ---------------- mma.sync fp16 GEMM, ldmatrix + cp.async double-buffer ----
 * C[18432, 768] = x @ Wcat^T. CTA: 128x128, 8 warps (4x2), warp tile 32x64.
 * K in 64-chunks; smem row stride 72 halves (144 B -> LDSM conflict-free).
 */
#define KST 72
#define TILE_BYTES (128 * KST * 2)          /* 18432 */
#define STAGE_BYTES (2 * TILE_BYTES)        /* A + B = 36864 */
#define SMEM_GEMM (2 * STAGE_BYTES)         /* 73728 -> 2 CTAs/SM */

__device__ __forceinline__ void mma16816(float* c, const uint32_t* a, const uint32_t* b) {
    asm volatile("mma.sync.aligned.m16n8k16.row.col.f32.f16.f16.f32 "
        "{%0,%1,%2,%3}, {%4,%5,%6,%7}, {%8,%9}, {%0,%1,%2,%3};"
        : "+f"(c[0]), "+f"(c[1]), "+f"(c[2]), "+f"(c[3])
        : "r"(a[0]), "r"(a[1]), "r"(a[2]), "r"(a[3]), "r"(b[0]), "r"(b[1]));
}
__device__ __forceinline__ void ldsm_x4(uint32_t* r, uint32_t addr) {
    asm volatile("ldmatrix.sync.aligned.m8n8.x4.shared.b16 {%0,%1,%2,%3}, [%4];"
        : "=r"(r[0]), "=r"(r[1]), "=r"(r[2]), "=r"(r[3]) : "r"(addr));
}
__device__ __forceinline__ void cp16(uint32_t dst, const void* src) {
    asm volatile("cp.async.cg.shared.global [%0], [%1], 16;" :: "r"(dst), "l"(src));
}
#define CP_COMMIT() asm volatile("cp.async.commit_group;" ::: "memory")
#define CP_WAIT(n)  asm volatile("cp.async.wait_group %0;" :: "n"(n) : "memory")

__device__ __forceinline__ uint32_t smem_u32(const void* p) {
    uint32_t a;
    asm("{ .reg .u64 t; cvta.to.shared.u64 t, %1; cvt.u32.u64 %0, t; }" : "=r"(a) : "l"(p));
    return a;
}

__global__ __launch_bounds__(256) void gemm_kernel(
    const float* __restrict__ bq, const float* __restrict__ bk, const float* __restrict__ bv)
{
    extern __shared__ char smc[];
    const uint32_t sb = smem_u32(smc);

    const int tid  = threadIdx.x;
    const int wid  = tid >> 5, lane = tid & 31;
    const int gid  = lane >> 2, tig = lane & 3;
    const int m0   = blockIdx.x * 128;
    const int n0   = blockIdx.y * 128;
    const int rbase = (wid & 3) * 32;
    const int nbase = (wid >> 2) * 64;

    /* per-lane ldmatrix quadrant offsets */
    const int mq = lane >> 3;
    const int laneRowA = (mq & 1) * 8 + (lane & 7);
    const int laneColA = (mq >> 1) * 8;
    const int laneRowB = (mq >> 1) * 8 + (lane & 7);
    const int laneColB = (mq & 1) * 8;

    /* staging addressing */
    const int sr = tid >> 3;          /* 0..31 (+32 per it) */
    const int sg = tid & 7;
    const uint32_t dstOff = (uint32_t)(sr * 144 + sg * 16);

    float c[2][8][4];
#pragma unroll
    for (int mt = 0; mt < 2; mt++)
#pragma unroll
        for (int nt = 0; nt < 8; nt++)
#pragma unroll
            for (int q = 0; q < 4; q++) c[mt][nt][q] = 0.f;

    auto stage = [&](int ch, int s) {
        const int k0 = ch * 64;
        const uint32_t base = sb + (uint32_t)s * STAGE_BYTES;
#pragma unroll
        for (int it = 0; it < 4; it++) {
            int r = sr + it * 32;
            size_t srcA = (size_t)(m0 + r) * 256 + k0 + sg * 8;
            size_t srcB = (size_t)(n0 + r) * 256 + k0 + sg * 8;
            uint32_t d = dstOff + (uint32_t)it * 32 * 144;
            cp16(base + d,              g_xh + srcA);
            cp16(base + TILE_BYTES + d, g_wt + srcB);
        }
    };

    stage(0, 0);
    CP_COMMIT();

    for (int ch = 0; ch < 4; ch++) {
        const int s = ch & 1;
        if (ch < 3) {
            stage(ch + 1, s ^ 1);
            CP_COMMIT();
            CP_WAIT(1);
        } else {
            CP_WAIT(0);
        }
        __syncthreads();

        const uint32_t aBase = sb + (uint32_t)s * STAGE_BYTES;
        const uint32_t bBase = aBase + TILE_BYTES;

#pragma unroll
        for (int ks = 0; ks < 4; ks++) {
            uint32_t a[2][4];
#pragma unroll
            for (int mt = 0; mt < 2; mt++) {
                uint32_t ao = (uint32_t)((rbase + mt * 16 + laneRowA) * KST
                                         + ks * 16 + laneColA) * 2;
                ldsm_x4(a[mt], aBase + ao);
            }
#pragma unroll
            for (int ntp = 0; ntp < 4; ntp++) {
                uint32_t bo = (uint32_t)((nbase + ntp * 16 + laneRowB) * KST
                                         + ks * 16 + laneColB) * 2;
                uint32_t bfr[4];
                ldsm_x4(bfr, bBase + bo);
#pragma unroll
                for (int mt = 0; mt < 2; mt++) {
                    mma16816(c[mt][2 * ntp],     a[mt], bfr);
                    mma16816(c[mt][2 * ntp + 1], a[mt], bfr + 2);
                }
            }
        }
        __syncthreads();
    }

    /* epilogue: bias (+relu on V), write head-major */
    const int sel = n0 >> 8;
    const float* bias = (sel == 0) ? bq : (sel == 1 ? bk : bv);
    const int bb = m0 / NTOK;
    const int tokbase = m0 % NTOK;
    float* outsel = g_qkv + ((size_t)(sel * 128 + bb * 8)) * NTOK * DHD;

#pragma unroll
    for (int mt = 0; mt < 2; mt++) {
        int r0 = tokbase + rbase + mt * 16 + gid;
#pragma unroll
        for (int nt = 0; nt < 8; nt++) {
            int cn = (n0 & 255) + nbase + nt * 8 + tig * 2;
            int h = cn >> 5, d = cn & 31;
            float bi0 = bias[cn], bi1 = bias[cn + 1];
            float v0 = c[mt][nt][0] + bi0, v1 = c[mt][nt][1] + bi1;
            float v2 = c[mt][nt][2] + bi0, v3 = c[mt][nt][3] + bi1;
            if (sel == 2) {
                v0 = fmaxf(v0, 0.f); v1 = fmaxf(v1, 0.f);
                v2 = fmaxf(v2, 0.f); v3 = fmaxf(v3, 0.f);
            }
            float* p0 = outsel + ((size_t)h * NTOK + r0) * DHD + d;
            *(float2*)p0 = make_float2(v0, v1);
            *(float2*)(p0 + 8 * DHD) = make_float2(v2, v3);
        }
    }
}

/* ---------------- attention: warp per (b, h, frame) — unchanged ------ */
#define SWST 28

__global__ __launch_bounds__(256) void attn_kernel(float* __restrict__ out)
{
    __shared__ float sw[8 * 32 * SWST];
    const int bh   = blockIdx.x;
    const int wid  = threadIdx.x >> 5;
    const int lane = threadIdx.x & 31;
    const int frame = blockIdx.y * 8 + wid;

    const float* qb = g_qkv + ((size_t)bh * NTOK + (size_t)frame * NJ) * DHD;
    const float* kb = g_qkv + ((size_t)(128 + bh) * NTOK + (size_t)frame * NJ) * DHD;
    const float* vb = g_qkv + ((size_t)(256 + bh) * NTOK + (size_t)frame * NJ) * DHD;

    float* sc = sw + wid * 32 * SWST;

#pragma unroll
    for (int r = 0; r < NJ; r++)
        sc[lane * SWST + r] = qb[r * DHD + lane];
    __syncwarp();

    const int j = (lane < NJ) ? lane : 0;
    float kreg[DHD];
    {
        const float4* kp = (const float4*)(kb + j * DHD);
#pragma unroll
        for (int cc = 0; cc < 8; cc++) {
            float4 kk = kp[cc];
            kreg[4*cc] = kk.x; kreg[4*cc+1] = kk.y; kreg[4*cc+2] = kk.z; kreg[4*cc+3] = kk.w;
        }
    }
    float s[NJ];
#pragma unroll
    for (int i = 0; i < NJ; i++) s[i] = 0.f;
#pragma unroll
    for (int d = 0; d < DHD; d++) {
        float kd = kreg[d];
#pragma unroll
        for (int i4 = 0; i4 < 6; i4++) {
            float4 q4 = *(const float4*)&sc[d * SWST + i4 * 4];
            s[i4*4+0] = fmaf(q4.x, kd, s[i4*4+0]);
            s[i4*4+1] = fmaf(q4.y, kd, s[i4*4+1]);
            s[i4*4+2] = fmaf(q4.z, kd, s[i4*4+2]);
            s[i4*4+3] = fmaf(q4.w, kd, s[i4*4+3]);
        }
    }
    const float scale = 0.17677669529663688f;
#pragma unroll
    for (int i = 0; i < NJ; i++)
        s[i] = (lane < NJ) ? s[i] * scale : -3.402823466e38f;

    __syncwarp();
    float w_[NJ];
#pragma unroll
    for (int i = 0; i < NJ; i++) {
        float m = s[i];
#pragma unroll
        for (int off = 16; off > 0; off >>= 1)
            m = fmaxf(m, __shfl_xor_sync(0xffffffffu, m, off));
        float e = __expf(s[i] - m);
        float sum = e;
#pragma unroll
        for (int off = 16; off > 0; off >>= 1)
            sum += __shfl_xor_sync(0xffffffffu, sum, off);
        w_[i] = e / (sum + EPSV);
    }

    if (lane < NJ) {
#pragma unroll
        for (int i = 0; i < NJ; i++)
            sc[lane * SWST + i] = w_[i];
    }
    __syncwarp();

    float vreg[NJ];
#pragma unroll
    for (int jj = 0; jj < NJ; jj++)
        vreg[jj] = vb[jj * DHD + lane];
    float o[NJ];
#pragma unroll
    for (int i = 0; i < NJ; i++) o[i] = 0.f;
#pragma unroll
    for (int jj = 0; jj < NJ; jj++) {
        float vj = vreg[jj];
#pragma unroll
        for (int i4 = 0; i4 < 6; i4++) {
            float4 a4 = *(const float4*)&sc[jj * SWST + i4 * 4];
            o[i4*4+0] = fmaf(a4.x, vj, o[i4*4+0]);
            o[i4*4+1] = fmaf(a4.y, vj, o[i4*4+1]);
            o[i4*4+2] = fmaf(a4.z, vj, o[i4*4+2]);
            o[i4*4+3] = fmaf(a4.w, vj, o[i4*4+3]);
        }
    }

    const int b = bh >> 3, h = bh & 7;
    float* od = out + ((size_t)b * NTOK + (size_t)frame * NJ) * DIN + h * DHD + lane;
#pragma unroll
    for (int i = 0; i < NJ; i++)
        od[(size_t)i * DIN] = o[i];
}

/* ---------------- launch ---------------- */
extern "C" void kernel_launch(void* const* d_in, const int* in_sizes, int n_in,
                              void* d_out, int out_size)
{
    const float* x  = (const float*)d_in[0];
    const float* Wq = (const float*)d_in[1];
    const float* bq = (const float*)d_in[2];
    const float* Wk = (const float*)d_in[3];
    const float* bk = (const float*)d_in[4];
    const float* Wv = (const float*)d_in[5];
    const float* bv = (const float*)d_in[6];
    float* out = (float*)d_out;

    cvt_kernel<<<4608 + 768, 256>>>(x, Wq, Wk, Wv);

    cudaFuncSetAttribute(gemm_kernel, cudaFuncAttributeMaxDynamicSharedMemorySize, SMEM_GEMM);
    gemm_kernel<<<dim3(144, 6), 256, SMEM_GEMM>>>(bq, bk, bv);

    attn_kernel<<<dim3(128, 6), 256>>>(out);
}